// round 6
// baseline (speedup 1.0000x reference)
#include <cuda_runtime.h>
#include <cuda_bf16.h>

typedef unsigned long long ULL;

#define HW 784
#define NPIX 3136

// ---------------------------------------------------------------------------
// accd layout (doubles): ds_sum@0, ds_ss@256, bn2_sum@512, bn2_ss@576,
// bn3_sum@640, bn3_ss@896, bn1_sum@1152, bn1_ss@1216.  total 1280.
// accf: ef[4]@0, el[4]@4, spl[4]@8.
// ---------------------------------------------------------------------------
struct __align__(16) Scratch {
    float f_ds[32768], f_c1[8192], f_c2[36864], f_c3[16384];
    float wmin[4], range[4];
    double accd[1280];
    float accf[12];
    float buf_ds[802816], buf_c3[802816];
    float buf_c1[200704], buf_peg[200704], buf_c2[200704];
};
__device__ Scratch g_s;

// ---------------- helpers --------------------------------------------------
__device__ __forceinline__ ULL addf2(ULL a, ULL b) {
    ULL r; asm("add.rn.f32x2 %0,%1,%2;" : "=l"(r) : "l"(a), "l"(b)); return r;
}
__device__ __forceinline__ ULL pack2(float v) {
    ULL r; unsigned u = __float_as_uint(v);
    asm("mov.b64 %0,{%1,%1};" : "=l"(r) : "r"(u)); return r;
}
__device__ __forceinline__ ULL packAB(float a, float b) {
    return ((ULL)__float_as_uint(b) << 32) | (ULL)__float_as_uint(a);
}
#define ABS2_MASK 0x7FFFFFFF7FFFFFFFULL

template<int BS>
__device__ __forceinline__ float blk_sum(float v) {
    __shared__ float red[BS / 32];
    #pragma unroll
    for (int o = 16; o > 0; o >>= 1) v += __shfl_xor_sync(0xffffffffu, v, o);
    int w = threadIdx.x >> 5, l = threadIdx.x & 31;
    if (l == 0) red[w] = v;
    __syncthreads();
    if (w == 0) {
        float s = (l < BS / 32) ? red[l] : 0.f;
        #pragma unroll
        for (int o = 16; o > 0; o >>= 1) s += __shfl_xor_sync(0xffffffffu, s, o);
        if (l == 0) red[0] = s;
    }
    __syncthreads();
    float r = red[0];
    __syncthreads();
    return r;
}

// ---------------- prep: zero accumulators + per-tensor min/max -------------
__global__ void __launch_bounds__(1024) prep_kernel(
    const float* __restrict__ w0, const float* __restrict__ w1,
    const float* __restrict__ w2, const float* __restrict__ w3)
{
    __shared__ float rmn[32], rmx[32];
    int tid = threadIdx.x, t = blockIdx.x;
    if (t == 0) {
        for (int i = tid; i < 1280; i += 1024) g_s.accd[i] = 0.0;
        if (tid < 12) g_s.accf[tid] = 0.f;
    }
    const float* w = (t==0)?w0:(t==1)?w1:(t==2)?w2:w3;
    int n4 = ((t==0)?32768:(t==1)?8192:(t==2)?36864:16384) >> 2;
    float mn = 3.4e38f, mx = -3.4e38f;
    for (int i = tid; i < n4; i += 1024) {
        float4 v = ((const float4*)w)[i];
        mn = fminf(mn, fminf(fminf(v.x, v.y), fminf(v.z, v.w)));
        mx = fmaxf(mx, fmaxf(fmaxf(v.x, v.y), fmaxf(v.z, v.w)));
    }
    #pragma unroll
    for (int o = 16; o > 0; o >>= 1) {
        mn = fminf(mn, __shfl_xor_sync(0xffffffffu, mn, o));
        mx = fmaxf(mx, __shfl_xor_sync(0xffffffffu, mx, o));
    }
    int wi = tid >> 5, l = tid & 31;
    if (l == 0) { rmn[wi] = mn; rmx[wi] = mx; }
    __syncthreads();
    if (wi == 0) {
        mn = rmn[l]; mx = rmx[l];
        #pragma unroll
        for (int o = 16; o > 0; o >>= 1) {
            mn = fminf(mn, __shfl_xor_sync(0xffffffffu, mn, o));
            mx = fmaxf(mx, __shfl_xor_sync(0xffffffffu, mx, o));
        }
        if (l == 0) { g_s.wmin[t] = mn; g_s.range[t] = mx - mn; }
    }
}

// ---------------- reconstruct weights + KL partials ------------------------
__global__ void __launch_bounds__(256) recon_kernel(
    const float* __restrict__ w0, const float* __restrict__ w1,
    const float* __restrict__ w2, const float* __restrict__ w3,
    const float* __restrict__ a0, const float* __restrict__ a1,
    const float* __restrict__ a2, const float* __restrict__ a3,
    const float* __restrict__ l0, const float* __restrict__ l1,
    const float* __restrict__ l2, const float* __restrict__ l3)
{
    int bid = blockIdx.x, tid = threadIdx.x;
    int t, lb;
    if (bid < 32)      { t = 0; lb = bid; }
    else if (bid < 40) { t = 1; lb = bid - 32; }
    else if (bid < 76) { t = 2; lb = bid - 40; }
    else               { t = 3; lb = bid - 76; }
    const float *w, *aff, *lap; float* f;
    if (t == 0)      { w = w0; aff = a0; lap = l0; f = g_s.f_ds; }
    else if (t == 1) { w = w1; aff = a1; lap = l1; f = g_s.f_c1; }
    else if (t == 2) { w = w2; aff = a2; lap = l2; f = g_s.f_c2; }
    else             { w = w3; aff = a3; lap = l3; f = g_s.f_c3; }

    float wmin = g_s.wmin[t], range = g_s.range[t];
    int i4 = lb * 256 + tid;
    float4 v4 = ((const float4*)w)[i4];
    float4 l4 = ((const float4*)lap)[i4];
    float vv[4] = {v4.x, v4.y, v4.z, v4.w};
    float ll[4] = {l4.x, l4.y, l4.z, l4.w};
    float fo[4];
    float ef = 0.f, el = 0.f, spl = 0.f;
    #pragma unroll
    for (int k = 0; k < 4; ++k) {
        float v = vv[k];
        float tt = (v - wmin) / range;            // same FP sequence as ref
        int idx = (int)floorf(tt * 100.0f);
        float val = (idx < 100) ? v * aff[idx] : 0.0f;
        fo[k] = val;
        float e = expf(ll[k]);
        ef += expf(val);
        el += e;
        spl += e * (ll[k] - val);
    }
    ((float4*)f)[i4] = make_float4(fo[0], fo[1], fo[2], fo[3]);
    float sef  = blk_sum<256>(ef);
    float sel  = blk_sum<256>(el);
    float sspl = blk_sum<256>(spl);
    if (tid == 0) {
        atomicAdd(&g_s.accf[t],     sef);
        atomicAdd(&g_s.accf[4 + t], sel);
        atomicAdd(&g_s.accf[8 + t], sspl);
    }
}

// ---------------- 1x1 adder: 128px x 2og, 16 outs/thread -------------------
// FUSED: yb<8 -> ds (stats), yb>=8 -> c1 (no stats).
template<int CIN, bool FUSED, bool BN_IN, bool STATS_T>
__global__ void __launch_bounds__(256) adder1x1_kernel(
    const float* __restrict__ in, const float* __restrict__ wsrc_a,
    float* __restrict__ out_a, int Cout_a,
    const double* __restrict__ bsum, const double* __restrict__ bss,
    const float* __restrict__ bg, const float* __restrict__ bb,
    double* __restrict__ osum_a, double* __restrict__ oss_a)
{
    __shared__ __align__(16) ULL wq[16 * CIN];   // [og][c][pr0..7]
    __shared__ float scale[CIN], shift[CIN];
    int tid = threadIdx.x;
    int b = blockIdx.z, yb = blockIdx.y;

    const float* wsrc; float* out; int Cout, o0; bool do_stats;
    double *osum, *oss;
    if (FUSED) {
        bool is_ds = yb < 8;
        wsrc = is_ds ? g_s.f_ds : g_s.f_c1;
        out  = is_ds ? g_s.buf_ds : g_s.buf_c1;
        Cout = is_ds ? 256 : 64;
        o0   = (is_ds ? yb : yb - 8) * 32;
        do_stats = is_ds;
        osum = g_s.accd; oss = g_s.accd + 256;
    } else {
        wsrc = wsrc_a; out = out_a; Cout = Cout_a; o0 = yb * 32;
        do_stats = STATS_T; osum = osum_a; oss = oss_a;
    }
    int p0 = blockIdx.x * 128;

    // interleaved packed weights: wq[(og*CIN + c)*8 + pr]
    for (int j = tid; j < 16 * CIN; j += 256) {
        int og = j / (8 * CIN), r = j - og * 8 * CIN;
        int c = r >> 3, pr = r & 7;
        int o = o0 + og * 16 + 2 * pr;
        wq[j] = packAB(-wsrc[o * CIN + c], -wsrc[(o + 1) * CIN + c]);
    }
    if (BN_IN) {
        if (tid < CIN) {
            double m = bsum[tid] * (1.0 / 3136.0);
            double var = bss[tid] * (1.0 / 3136.0) - m * m;
            float istd = rsqrtf((float)var + 1e-5f);
            float sc = istd * bg[tid];
            scale[tid] = sc;
            shift[tid] = bb[tid] - (float)m * sc;
        }
    }
    __syncthreads();

    int px = tid & 127, og = tid >> 7;
    int p = p0 + px;
    bool valid = p < HW;
    int pc = valid ? p : (HW - 1);

    const float* xp = in + (size_t)b * CIN * HW + pc;
    const ULL* wp = wq + og * 8 * CIN;
    ULL acc[8];
    #pragma unroll
    for (int k = 0; k < 8; ++k) acc[k] = 0;

    #pragma unroll 4
    for (int c = 0; c < CIN; ++c) {
        float xv = xp[(size_t)c * HW];
        if (BN_IN) xv = fmaxf(fmaf(xv, scale[c], shift[c]), 0.0f);
        ULL xx = pack2(xv);
        const ulonglong2* wc = (const ulonglong2*)(wp + c * 8);
        #pragma unroll
        for (int q = 0; q < 4; ++q) {
            ulonglong2 ww = wc[q];
            acc[2 * q]     = addf2(acc[2 * q],     addf2(xx, ww.x) & ABS2_MASK);
            acc[2 * q + 1] = addf2(acc[2 * q + 1], addf2(xx, ww.y) & ABS2_MASK);
        }
    }

    float a[16];
    #pragma unroll
    for (int k = 0; k < 8; ++k) {
        a[2 * k]     = __uint_as_float((unsigned)acc[k]);
        a[2 * k + 1] = __uint_as_float((unsigned)(acc[k] >> 32));
    }
    int ob = o0 + og * 16;
    if (valid) {
        #pragma unroll
        for (int k = 0; k < 16; ++k)
            out[((size_t)b * Cout + ob + k) * HW + p] = -a[k];
    }
    if (do_stats) {
        #pragma unroll
        for (int k = 0; k < 16; ++k) {
            float s  = valid ? -a[k] : 0.0f;
            float s2 = valid ? a[k] * a[k] : 0.0f;
            #pragma unroll
            for (int o = 16; o > 0; o >>= 1) {
                s  += __shfl_xor_sync(0xffffffffu, s,  o);
                s2 += __shfl_xor_sync(0xffffffffu, s2, o);
            }
            if ((tid & 31) == 0) {
                atomicAdd(&osum[ob + k], (double)s);
                atomicAdd(&oss[ob + k],  (double)s2);
            }
        }
    }
}

// ---------------- 3x3 adder: 128px x 2og, 8 outs/thread, BN_IN(bn1) --------
// grid (7, 4, 4); weight tile 16 outs, 36 KB.
__global__ void __launch_bounds__(256) adder3x3_kernel(
    const float* __restrict__ in, const float* __restrict__ wsrc,
    float* __restrict__ out,
    const double* __restrict__ bsum, const double* __restrict__ bss,
    const float* __restrict__ bg, const float* __restrict__ bb,
    double* __restrict__ osum, double* __restrict__ oss)
{
    __shared__ __align__(16) ULL wq[4608];   // [og][ct][kp0..3]
    __shared__ float scale[64], shift[64];
    int tid = threadIdx.x;
    int b = blockIdx.z, o0 = blockIdx.y * 16, p0 = blockIdx.x * 128;

    for (int j = tid; j < 4608; j += 256) {
        int og = j / 2304, r = j - og * 2304;
        int ct = r >> 2, kp = r & 3;
        int o = o0 + og * 8 + 2 * kp;
        wq[j] = packAB(-wsrc[o * 576 + ct], -wsrc[(o + 1) * 576 + ct]);
    }
    if (tid < 64) {
        double m = bsum[tid] * (1.0 / 3136.0);
        double var = bss[tid] * (1.0 / 3136.0) - m * m;
        float istd = rsqrtf((float)var + 1e-5f);
        float sc = istd * bg[tid];
        scale[tid] = sc;
        shift[tid] = bb[tid] - (float)m * sc;
    }
    __syncthreads();

    int px = tid & 127, og = tid >> 7;
    int p = p0 + px;
    bool valid = p < HW;
    int pc = valid ? p : (HW - 1);
    int y = pc / 28, x = pc - y * 28;

    int off[9]; bool vld[9];
    #pragma unroll
    for (int t = 0; t < 9; ++t) {
        int yy = y + t / 3 - 1, xx = x + t % 3 - 1;
        vld[t] = (yy >= 0 && yy < 28 && xx >= 0 && xx < 28);
        off[t] = yy * 28 + xx;
    }

    const ULL* wp = wq + og * 2304;
    ULL acc[4];
    #pragma unroll
    for (int k = 0; k < 4; ++k) acc[k] = 0;

    for (int c = 0; c < 64; ++c) {
        const float* ip = in + ((size_t)(b * 64 + c)) * HW;
        float sc = scale[c], sh = shift[c];
        float v[9];
        #pragma unroll
        for (int t = 0; t < 9; ++t)
            v[t] = vld[t] ? fmaxf(fmaf(ip[off[t]], sc, sh), 0.0f) : 0.0f;
        const ulonglong2* wc = (const ulonglong2*)(wp + c * 36);
        #pragma unroll
        for (int t = 0; t < 9; ++t) {
            ULL xx2 = pack2(v[t]);
            ulonglong2 w01 = wc[2 * t];
            ulonglong2 w23 = wc[2 * t + 1];
            acc[0] = addf2(acc[0], addf2(xx2, w01.x) & ABS2_MASK);
            acc[1] = addf2(acc[1], addf2(xx2, w01.y) & ABS2_MASK);
            acc[2] = addf2(acc[2], addf2(xx2, w23.x) & ABS2_MASK);
            acc[3] = addf2(acc[3], addf2(xx2, w23.y) & ABS2_MASK);
        }
    }

    float a[8];
    #pragma unroll
    for (int k = 0; k < 4; ++k) {
        a[2 * k]     = __uint_as_float((unsigned)acc[k]);
        a[2 * k + 1] = __uint_as_float((unsigned)(acc[k] >> 32));
    }
    int ob = o0 + og * 8;
    if (valid) {
        #pragma unroll
        for (int k = 0; k < 8; ++k)
            out[((size_t)b * 64 + ob + k) * HW + p] = -a[k];
    }
    #pragma unroll
    for (int k = 0; k < 8; ++k) {
        float s  = valid ? -a[k] : 0.0f;
        float s2 = valid ? a[k] * a[k] : 0.0f;
        #pragma unroll
        for (int o = 16; o > 0; o >>= 1) {
            s  += __shfl_xor_sync(0xffffffffu, s,  o);
            s2 += __shfl_xor_sync(0xffffffffu, s2, o);
        }
        if ((tid & 31) == 0) {
            atomicAdd(&osum[ob + k], (double)s);
            atomicAdd(&oss[ob + k],  (double)s2);
        }
    }
}

// ---------------- PEG depthwise 3x3: wide (256 blocks) + bn1 stats ---------
__global__ void __launch_bounds__(256) peg_kernel(
    const float* __restrict__ in, const float* __restrict__ pw,
    float* __restrict__ out, double* __restrict__ osum, double* __restrict__ oss)
{
    int ch = blockIdx.x & 63, b = blockIdx.x >> 6;
    int tid = threadIdx.x;
    const float* ip = in + ((size_t)(b * 64 + ch)) * HW;
    float* op = out + ((size_t)(b * 64 + ch)) * HW;

    float wc[9];
    #pragma unroll
    for (int t = 0; t < 9; ++t) wc[t] = pw[ch * 9 + t];

    float s = 0.f, s2 = 0.f;
    #pragma unroll
    for (int it = 0; it < 4; ++it) {
        int p = tid + it * 256;
        if (p < HW) {
            int y = p / 28, x = p - y * 28;
            float acc = 0.f;
            #pragma unroll
            for (int t = 0; t < 9; ++t) {
                int yy = y + t / 3 - 1, xx = x + t % 3 - 1;
                float v = (yy >= 0 && yy < 28 && xx >= 0 && xx < 28)
                          ? ip[yy * 28 + xx] : 0.0f;
                acc += fabsf(v - wc[t]);
            }
            op[p] = -acc;
            s += -acc;
            s2 += acc * acc;
        }
    }
    float ts  = blk_sum<256>(s);
    float ts2 = blk_sum<256>(s2);
    if (tid == 0) {
        atomicAdd(&osum[ch], (double)ts);
        atomicAdd(&oss[ch],  (double)ts2);
    }
}

// ---------------- final: bn3/bnds + residual + relu + KL -------------------
__global__ void __launch_bounds__(256) final_kernel(
    const float* __restrict__ g3, const float* __restrict__ b3,
    const float* __restrict__ gds, const float* __restrict__ bds,
    float* __restrict__ out, int out_size)
{
    int idx4 = blockIdx.x * 256 + threadIdx.x;
    if (idx4 == 0 && out_size > 802816) {
        const float ns[4] = {32768.f, 8192.f, 36864.f, 16384.f};
        float kl = 0.f;
        #pragma unroll
        for (int t = 0; t < 4; ++t) {
            float ef = g_s.accf[t], el = g_s.accf[4 + t], spl = g_s.accf[8 + t];
            kl += (spl / el + logf(ef) - logf(el)) / ns[t];
        }
        out[802816] = kl;
    }
    size_t base = (size_t)idx4 * 4;
    int ch = (int)((base / HW) & 255);

    double m3d = g_s.accd[640 + ch] * (1.0 / 3136.0);
    double v3d = g_s.accd[896 + ch] * (1.0 / 3136.0) - m3d * m3d;
    float m3 = (float)m3d, istd3 = rsqrtf((float)v3d + 1e-5f);
    float sc3 = istd3 * g3[ch], sh3 = b3[ch] - m3 * sc3;

    double mdd = g_s.accd[0 + ch] * (1.0 / 3136.0);
    double vdd = g_s.accd[256 + ch] * (1.0 / 3136.0) - mdd * mdd;
    float md = (float)mdd, istdd = rsqrtf((float)vdd + 1e-5f);
    float scd = istdd * gds[ch], shd = bds[ch] - md * scd;

    float4 a = *(const float4*)(g_s.buf_c3 + base);
    float4 d = *(const float4*)(g_s.buf_ds + base);
    float4 o;
    o.x = fmaxf(fmaf(a.x, sc3, sh3) + fmaxf(fmaf(d.x, scd, shd), 0.f), 0.f);
    o.y = fmaxf(fmaf(a.y, sc3, sh3) + fmaxf(fmaf(d.y, scd, shd), 0.f), 0.f);
    o.z = fmaxf(fmaf(a.z, sc3, sh3) + fmaxf(fmaf(d.z, scd, shd), 0.f), 0.f);
    o.w = fmaxf(fmaf(a.w, sc3, sh3) + fmaxf(fmaf(d.w, scd, shd), 0.f), 0.f);
    *(float4*)(out + base) = o;
}

// ---------------------------------------------------------------------------
extern "C" void kernel_launch(void* const* d_in, const int* in_sizes, int n_in,
                              void* d_out, int out_size)
{
    const float* x    = (const float*)d_in[0];
    const float* w_ds = (const float*)d_in[1];
    const float* w_c1 = (const float*)d_in[2];
    const float* w_c2 = (const float*)d_in[3];
    const float* w_c3 = (const float*)d_in[4];
    const float* a_ds = (const float*)d_in[5];
    const float* a_c1 = (const float*)d_in[6];
    const float* a_c2 = (const float*)d_in[7];
    const float* a_c3 = (const float*)d_in[8];
    const float* pegw = (const float*)d_in[9];
    const float* g1   = (const float*)d_in[10];
    const float* b1   = (const float*)d_in[11];
    const float* g2   = (const float*)d_in[12];
    const float* b2   = (const float*)d_in[13];
    const float* g3   = (const float*)d_in[14];
    const float* b3   = (const float*)d_in[15];
    const float* gds  = (const float*)d_in[16];
    const float* bds  = (const float*)d_in[17];
    const float* lds  = (const float*)d_in[18];
    const float* lc1  = (const float*)d_in[19];
    const float* lc2  = (const float*)d_in[20];
    const float* lc3  = (const float*)d_in[21];
    float* out = (float*)d_out;

    Scratch* s = nullptr;
    cudaGetSymbolAddress((void**)&s, g_s);

    // 1) zero accumulators + per-tensor weight min/max
    prep_kernel<<<4, 1024>>>(w_ds, w_c1, w_c2, w_c3);

    // 2) bin-reconstruct all weights + KL partial sums
    recon_kernel<<<92, 256>>>(w_ds, w_c1, w_c2, w_c3,
                              a_ds, a_c1, a_c2, a_c3,
                              lds, lc1, lc2, lc3);

    // 3) fused ds (y<8, +bnds stats) and c1 (y=8..9) over x
    adder1x1_kernel<128, true, false, false><<<dim3(7, 10, 4), 256>>>(
        x, nullptr, nullptr, 0,
        nullptr, nullptr, nullptr, nullptr, nullptr, nullptr);

    // 4) PEG depthwise (wide) + bn1 stats
    peg_kernel<<<256, 256>>>(s->buf_c1, pegw, s->buf_peg,
                             s->accd + 1152, s->accd + 1216);

    // 5) conv2 3x3 with inline bn1+relu on input (+ bn2 stats)
    adder3x3_kernel<<<dim3(7, 4, 4), 256>>>(
        s->buf_peg, s->f_c2, s->buf_c2,
        s->accd + 1152, s->accd + 1216, g1, b1,
        s->accd + 512, s->accd + 576);

    // 6) conv3 1x1 with inline bn2+relu on input (+ bn3 stats)
    adder1x1_kernel<64, false, true, true><<<dim3(7, 8, 4), 256>>>(
        s->buf_c2, s->f_c3, s->buf_c3, 256,
        s->accd + 512, s->accd + 576, g2, b2, s->accd + 640, s->accd + 896);

    // 7) fused epilogue: bn3 + relu(bnds) residual + relu, and KL scalar
    final_kernel<<<784, 256>>>(g3, b3, gds, bds, out, out_size);
}

// round 7
// speedup vs baseline: 1.1344x; 1.1344x over previous
#include <cuda_runtime.h>
#include <cuda_bf16.h>

typedef unsigned long long ULL;

#define HW 784
#define NPIX 3136

// ---------------------------------------------------------------------------
// accd layout (doubles): ds_sum@0, ds_ss@256, bn2_sum@512, bn2_ss@576,
// bn3_sum@640, bn3_ss@896, bn1_sum@1152, bn1_ss@1216.  total 1280.
// accf: ef[4]@0, el[4]@4, spl[4]@8.
// ---------------------------------------------------------------------------
struct __align__(16) Scratch {
    float f_ds[32768], f_c1[8192], f_c2[36864], f_c3[16384];
    float wmin[4], range[4];
    double accd[1280];
    float accf[12];
    float buf_ds[802816], buf_c3[802816];
    float buf_c1[200704], buf_peg[200704], buf_c2[200704];
};
__device__ Scratch g_s;

// ---------------- helpers --------------------------------------------------
__device__ __forceinline__ ULL addf2(ULL a, ULL b) {
    ULL r; asm("add.rn.f32x2 %0,%1,%2;" : "=l"(r) : "l"(a), "l"(b)); return r;
}
__device__ __forceinline__ ULL pack2(float v) {
    ULL r; unsigned u = __float_as_uint(v);
    asm("mov.b64 %0,{%1,%1};" : "=l"(r) : "r"(u)); return r;
}
__device__ __forceinline__ ULL packAB(float a, float b) {
    return ((ULL)__float_as_uint(b) << 32) | (ULL)__float_as_uint(a);
}
#define ABS2_MASK 0x7FFFFFFF7FFFFFFFULL

template<int BS>
__device__ __forceinline__ float blk_sum(float v) {
    __shared__ float red[BS / 32];
    #pragma unroll
    for (int o = 16; o > 0; o >>= 1) v += __shfl_xor_sync(0xffffffffu, v, o);
    int w = threadIdx.x >> 5, l = threadIdx.x & 31;
    if (l == 0) red[w] = v;
    __syncthreads();
    if (w == 0) {
        float s = (l < BS / 32) ? red[l] : 0.f;
        #pragma unroll
        for (int o = 16; o > 0; o >>= 1) s += __shfl_xor_sync(0xffffffffu, s, o);
        if (l == 0) red[0] = s;
    }
    __syncthreads();
    float r = red[0];
    __syncthreads();
    return r;
}

// ---------------- prep: zero accumulators + per-tensor min/max -------------
__global__ void __launch_bounds__(1024) prep_kernel(
    const float* __restrict__ w0, const float* __restrict__ w1,
    const float* __restrict__ w2, const float* __restrict__ w3)
{
    __shared__ float rmn[32], rmx[32];
    int tid = threadIdx.x, t = blockIdx.x;
    if (t == 0) {
        for (int i = tid; i < 1280; i += 1024) g_s.accd[i] = 0.0;
        if (tid < 12) g_s.accf[tid] = 0.f;
    }
    const float* w = (t==0)?w0:(t==1)?w1:(t==2)?w2:w3;
    int n4 = ((t==0)?32768:(t==1)?8192:(t==2)?36864:16384) >> 2;
    float mn = 3.4e38f, mx = -3.4e38f;
    for (int i = tid; i < n4; i += 1024) {
        float4 v = ((const float4*)w)[i];
        mn = fminf(mn, fminf(fminf(v.x, v.y), fminf(v.z, v.w)));
        mx = fmaxf(mx, fmaxf(fmaxf(v.x, v.y), fmaxf(v.z, v.w)));
    }
    #pragma unroll
    for (int o = 16; o > 0; o >>= 1) {
        mn = fminf(mn, __shfl_xor_sync(0xffffffffu, mn, o));
        mx = fmaxf(mx, __shfl_xor_sync(0xffffffffu, mx, o));
    }
    int wi = tid >> 5, l = tid & 31;
    if (l == 0) { rmn[wi] = mn; rmx[wi] = mx; }
    __syncthreads();
    if (wi == 0) {
        mn = rmn[l]; mx = rmx[l];
        #pragma unroll
        for (int o = 16; o > 0; o >>= 1) {
            mn = fminf(mn, __shfl_xor_sync(0xffffffffu, mn, o));
            mx = fmaxf(mx, __shfl_xor_sync(0xffffffffu, mx, o));
        }
        if (l == 0) { g_s.wmin[t] = mn; g_s.range[t] = mx - mn; }
    }
}

// ---------------- reconstruct weights + KL partials ------------------------
__global__ void __launch_bounds__(256) recon_kernel(
    const float* __restrict__ w0, const float* __restrict__ w1,
    const float* __restrict__ w2, const float* __restrict__ w3,
    const float* __restrict__ a0, const float* __restrict__ a1,
    const float* __restrict__ a2, const float* __restrict__ a3,
    const float* __restrict__ l0, const float* __restrict__ l1,
    const float* __restrict__ l2, const float* __restrict__ l3)
{
    int bid = blockIdx.x, tid = threadIdx.x;
    int t, lb;
    if (bid < 32)      { t = 0; lb = bid; }
    else if (bid < 40) { t = 1; lb = bid - 32; }
    else if (bid < 76) { t = 2; lb = bid - 40; }
    else               { t = 3; lb = bid - 76; }
    const float *w, *aff, *lap; float* f;
    if (t == 0)      { w = w0; aff = a0; lap = l0; f = g_s.f_ds; }
    else if (t == 1) { w = w1; aff = a1; lap = l1; f = g_s.f_c1; }
    else if (t == 2) { w = w2; aff = a2; lap = l2; f = g_s.f_c2; }
    else             { w = w3; aff = a3; lap = l3; f = g_s.f_c3; }

    float wmin = g_s.wmin[t], range = g_s.range[t];
    int i4 = lb * 256 + tid;
    float4 v4 = ((const float4*)w)[i4];
    float4 l4 = ((const float4*)lap)[i4];
    float vv[4] = {v4.x, v4.y, v4.z, v4.w};
    float ll[4] = {l4.x, l4.y, l4.z, l4.w};
    float fo[4];
    float ef = 0.f, el = 0.f, spl = 0.f;
    #pragma unroll
    for (int k = 0; k < 4; ++k) {
        float v = vv[k];
        float tt = (v - wmin) / range;            // same FP sequence as ref
        int idx = (int)floorf(tt * 100.0f);
        float val = (idx < 100) ? v * aff[idx] : 0.0f;
        fo[k] = val;
        float e = expf(ll[k]);
        ef += expf(val);
        el += e;
        spl += e * (ll[k] - val);
    }
    ((float4*)f)[i4] = make_float4(fo[0], fo[1], fo[2], fo[3]);
    float sef  = blk_sum<256>(ef);
    float sel  = blk_sum<256>(el);
    float sspl = blk_sum<256>(spl);
    if (tid == 0) {
        atomicAdd(&g_s.accf[t],     sef);
        atomicAdd(&g_s.accf[4 + t], sel);
        atomicAdd(&g_s.accf[8 + t], sspl);
    }
}

// ---------------- generic 1x1 adder (f32x2, LDS.128 weights) ---------------
// 256 thr = 64 px x 4 og; each og handles 8 outputs (4 pairs).
// FUSED: blockIdx.y selects ds (y<8, stats) vs c1 (y>=8, no stats).
template<int CIN, bool FUSED, bool BN_IN, bool STATS_T>
__global__ void __launch_bounds__(256) adder1x1_kernel(
    const float* __restrict__ in, const float* __restrict__ wsrc_a,
    float* __restrict__ out_a, int Cout_a,
    const double* __restrict__ bsum, const double* __restrict__ bss,
    const float* __restrict__ bg, const float* __restrict__ bb,
    double* __restrict__ osum_a, double* __restrict__ oss_a)
{
    __shared__ __align__(16) ULL wq[16 * CIN];   // [og][c][pr]
    __shared__ float scale[CIN], shift[CIN];
    int tid = threadIdx.x;
    int b = blockIdx.z, yb = blockIdx.y;

    const float* wsrc; float* out; int Cout, o0; bool do_stats;
    double *osum, *oss;
    if (FUSED) {
        bool is_ds = yb < 8;
        wsrc = is_ds ? g_s.f_ds : g_s.f_c1;
        out  = is_ds ? g_s.buf_ds : g_s.buf_c1;
        Cout = is_ds ? 256 : 64;
        o0   = (is_ds ? yb : yb - 8) * 32;
        do_stats = is_ds;
        osum = g_s.accd; oss = g_s.accd + 256;
    } else {
        wsrc = wsrc_a; out = out_a; Cout = Cout_a; o0 = yb * 32;
        do_stats = STATS_T; osum = osum_a; oss = oss_a;
    }
    int p0 = blockIdx.x * 64;

    // build interleaved packed weights: wq[((og*CIN + c)*4) + pr]
    for (int j = tid; j < 16 * CIN; j += 256) {
        int og = j / (4 * CIN), r = j - og * 4 * CIN;
        int c = r >> 2, pr = r & 3;
        int o = o0 + og * 8 + 2 * pr;
        wq[j] = packAB(-wsrc[o * CIN + c], -wsrc[(o + 1) * CIN + c]);
    }
    if (BN_IN) {
        if (tid < CIN) {
            double m = bsum[tid] * (1.0 / 3136.0);
            double var = bss[tid] * (1.0 / 3136.0) - m * m;
            float istd = rsqrtf((float)var + 1e-5f);
            float sc = istd * bg[tid];
            scale[tid] = sc;
            shift[tid] = bb[tid] - (float)m * sc;
        }
    }
    __syncthreads();

    int px = tid & 63, og = tid >> 6;
    int p = p0 + px;
    bool valid = p < HW;
    int pc = valid ? p : (HW - 1);

    const float* xp = in + (size_t)b * CIN * HW + pc;
    const ULL* wp = wq + og * 4 * CIN;
    ULL acc0 = 0, acc1 = 0, acc2 = 0, acc3 = 0;

    #pragma unroll 4
    for (int c = 0; c < CIN; ++c) {
        float xv = xp[(size_t)c * HW];
        if (BN_IN) xv = fmaxf(fmaf(xv, scale[c], shift[c]), 0.0f);
        ULL xx = pack2(xv);
        ulonglong2 w01 = *(const ulonglong2*)(wp + c * 4);
        ulonglong2 w23 = *(const ulonglong2*)(wp + c * 4 + 2);
        acc0 = addf2(acc0, addf2(xx, w01.x) & ABS2_MASK);
        acc1 = addf2(acc1, addf2(xx, w01.y) & ABS2_MASK);
        acc2 = addf2(acc2, addf2(xx, w23.x) & ABS2_MASK);
        acc3 = addf2(acc3, addf2(xx, w23.y) & ABS2_MASK);
    }

    float a[8];
    a[0] = __uint_as_float((unsigned)acc0); a[1] = __uint_as_float((unsigned)(acc0 >> 32));
    a[2] = __uint_as_float((unsigned)acc1); a[3] = __uint_as_float((unsigned)(acc1 >> 32));
    a[4] = __uint_as_float((unsigned)acc2); a[5] = __uint_as_float((unsigned)(acc2 >> 32));
    a[6] = __uint_as_float((unsigned)acc3); a[7] = __uint_as_float((unsigned)(acc3 >> 32));
    int ob = o0 + og * 8;
    if (valid) {
        #pragma unroll
        for (int k = 0; k < 8; ++k)
            out[((size_t)b * Cout + ob + k) * HW + p] = -a[k];
    }
    if (do_stats) {
        #pragma unroll
        for (int k = 0; k < 8; ++k) {
            float s  = valid ? -a[k] : 0.0f;
            float s2 = valid ? a[k] * a[k] : 0.0f;
            #pragma unroll
            for (int o = 16; o > 0; o >>= 1) {
                s  += __shfl_xor_sync(0xffffffffu, s,  o);
                s2 += __shfl_xor_sync(0xffffffffu, s2, o);
            }
            if ((tid & 31) == 0) {
                atomicAdd(&osum[ob + k], (double)s);
                atomicAdd(&oss[ob + k],  (double)s2);
            }
        }
    }
}

// ---------------- 3x3 adder (64->64, pad 1), bn1 folded on input -----------
// 256 thr = 64 px x 4 og; og handles 4 outputs (2 pairs). grid (13,4,4).
__global__ void __launch_bounds__(256) adder3x3_kernel(
    const float* __restrict__ in, const float* __restrict__ wsrc,
    float* __restrict__ out,
    const double* __restrict__ bsum, const double* __restrict__ bss,
    const float* __restrict__ bg, const float* __restrict__ bb,
    double* __restrict__ osum, double* __restrict__ oss)
{
    __shared__ __align__(16) ULL wq[4608];   // [og][ct][kp], 36 KB
    __shared__ float scale[64], shift[64];
    int tid = threadIdx.x;
    int b = blockIdx.z, o0 = blockIdx.y * 16, p0 = blockIdx.x * 64;

    for (int j = tid; j < 4608; j += 256) {
        int og = j / 1152, r = j - og * 1152;
        int ct = r >> 1, kp = r & 1;
        int o = o0 + og * 4 + 2 * kp;
        wq[j] = packAB(-wsrc[o * 576 + ct], -wsrc[(o + 1) * 576 + ct]);
    }
    if (tid < 64) {
        double m = bsum[tid] * (1.0 / 3136.0);
        double var = bss[tid] * (1.0 / 3136.0) - m * m;
        float istd = rsqrtf((float)var + 1e-5f);
        float sc = istd * bg[tid];
        scale[tid] = sc;
        shift[tid] = bb[tid] - (float)m * sc;
    }
    __syncthreads();

    int px = tid & 63, og = tid >> 6;
    int p = p0 + px;
    bool valid = p < HW;
    int pc = valid ? p : (HW - 1);
    int y = pc / 28, x = pc - y * 28;

    int off[9]; bool vld[9];
    #pragma unroll
    for (int t = 0; t < 9; ++t) {
        int yy = y + t / 3 - 1, xx = x + t % 3 - 1;
        vld[t] = (yy >= 0 && yy < 28 && xx >= 0 && xx < 28);
        off[t] = yy * 28 + xx;
    }

    const ulonglong2* wp = (const ulonglong2*)(wq + og * 1152);
    ULL acc0 = 0, acc1 = 0;

    for (int c = 0; c < 64; ++c) {
        const float* ip = in + ((size_t)(b * 64 + c)) * HW;
        float sc = scale[c], sh = shift[c];
        float v[9];
        #pragma unroll
        for (int t = 0; t < 9; ++t)
            v[t] = vld[t] ? fmaxf(fmaf(ip[off[t]], sc, sh), 0.0f) : 0.0f;
        const ulonglong2* wc = wp + c * 9;
        #pragma unroll
        for (int t = 0; t < 9; ++t) {
            ULL xx2 = pack2(v[t]);
            ulonglong2 ww = wc[t];
            acc0 = addf2(acc0, addf2(xx2, ww.x) & ABS2_MASK);
            acc1 = addf2(acc1, addf2(xx2, ww.y) & ABS2_MASK);
        }
    }

    float a[4];
    a[0] = __uint_as_float((unsigned)acc0); a[1] = __uint_as_float((unsigned)(acc0 >> 32));
    a[2] = __uint_as_float((unsigned)acc1); a[3] = __uint_as_float((unsigned)(acc1 >> 32));
    int ob = o0 + og * 4;
    if (valid) {
        #pragma unroll
        for (int k = 0; k < 4; ++k)
            out[((size_t)b * 64 + ob + k) * HW + p] = -a[k];
    }
    #pragma unroll
    for (int k = 0; k < 4; ++k) {
        float s  = valid ? -a[k] : 0.0f;
        float s2 = valid ? a[k] * a[k] : 0.0f;
        #pragma unroll
        for (int o = 16; o > 0; o >>= 1) {
            s  += __shfl_xor_sync(0xffffffffu, s,  o);
            s2 += __shfl_xor_sync(0xffffffffu, s2, o);
        }
        if ((tid & 31) == 0) {
            atomicAdd(&osum[ob + k], (double)s);
            atomicAdd(&oss[ob + k],  (double)s2);
        }
    }
}

// ---------------- PEG depthwise 3x3: wide (256 blocks) + bn1 stats ---------
__global__ void __launch_bounds__(256) peg_kernel(
    const float* __restrict__ in, const float* __restrict__ pw,
    float* __restrict__ out, double* __restrict__ osum, double* __restrict__ oss)
{
    int ch = blockIdx.x & 63, b = blockIdx.x >> 6;
    int tid = threadIdx.x;
    const float* ip = in + ((size_t)(b * 64 + ch)) * HW;
    float* op = out + ((size_t)(b * 64 + ch)) * HW;

    float wc[9];
    #pragma unroll
    for (int t = 0; t < 9; ++t) wc[t] = pw[ch * 9 + t];

    float s = 0.f, s2 = 0.f;
    #pragma unroll
    for (int it = 0; it < 4; ++it) {
        int p = tid + it * 256;
        if (p < HW) {
            int y = p / 28, x = p - y * 28;
            float acc = 0.f;
            #pragma unroll
            for (int t = 0; t < 9; ++t) {
                int yy = y + t / 3 - 1, xx = x + t % 3 - 1;
                float v = (yy >= 0 && yy < 28 && xx >= 0 && xx < 28)
                          ? ip[yy * 28 + xx] : 0.0f;
                acc += fabsf(v - wc[t]);
            }
            op[p] = -acc;
            s += -acc;
            s2 += acc * acc;
        }
    }
    float ts  = blk_sum<256>(s);
    float ts2 = blk_sum<256>(s2);
    if (tid == 0) {
        atomicAdd(&osum[ch], (double)ts);
        atomicAdd(&oss[ch],  (double)ts2);
    }
}

// ---------------- final: bn3/bnds + residual + relu + KL -------------------
__global__ void __launch_bounds__(256) final_kernel(
    const float* __restrict__ g3, const float* __restrict__ b3,
    const float* __restrict__ gds, const float* __restrict__ bds,
    float* __restrict__ out, int out_size)
{
    int idx4 = blockIdx.x * 256 + threadIdx.x;
    if (idx4 == 0 && out_size > 802816) {
        const float ns[4] = {32768.f, 8192.f, 36864.f, 16384.f};
        float kl = 0.f;
        #pragma unroll
        for (int t = 0; t < 4; ++t) {
            float ef = g_s.accf[t], el = g_s.accf[4 + t], spl = g_s.accf[8 + t];
            kl += (spl / el + logf(ef) - logf(el)) / ns[t];
        }
        out[802816] = kl;
    }
    size_t base = (size_t)idx4 * 4;
    int ch = (int)((base / HW) & 255);

    double m3d = g_s.accd[640 + ch] * (1.0 / 3136.0);
    double v3d = g_s.accd[896 + ch] * (1.0 / 3136.0) - m3d * m3d;
    float m3 = (float)m3d, istd3 = rsqrtf((float)v3d + 1e-5f);
    float sc3 = istd3 * g3[ch], sh3 = b3[ch] - m3 * sc3;

    double mdd = g_s.accd[0 + ch] * (1.0 / 3136.0);
    double vdd = g_s.accd[256 + ch] * (1.0 / 3136.0) - mdd * mdd;
    float md = (float)mdd, istdd = rsqrtf((float)vdd + 1e-5f);
    float scd = istdd * gds[ch], shd = bds[ch] - md * scd;

    float4 a = *(const float4*)(g_s.buf_c3 + base);
    float4 d = *(const float4*)(g_s.buf_ds + base);
    float4 o;
    o.x = fmaxf(fmaf(a.x, sc3, sh3) + fmaxf(fmaf(d.x, scd, shd), 0.f), 0.f);
    o.y = fmaxf(fmaf(a.y, sc3, sh3) + fmaxf(fmaf(d.y, scd, shd), 0.f), 0.f);
    o.z = fmaxf(fmaf(a.z, sc3, sh3) + fmaxf(fmaf(d.z, scd, shd), 0.f), 0.f);
    o.w = fmaxf(fmaf(a.w, sc3, sh3) + fmaxf(fmaf(d.w, scd, shd), 0.f), 0.f);
    *(float4*)(out + base) = o;
}

// ---------------------------------------------------------------------------
extern "C" void kernel_launch(void* const* d_in, const int* in_sizes, int n_in,
                              void* d_out, int out_size)
{
    const float* x    = (const float*)d_in[0];
    const float* w_ds = (const float*)d_in[1];
    const float* w_c1 = (const float*)d_in[2];
    const float* w_c2 = (const float*)d_in[3];
    const float* w_c3 = (const float*)d_in[4];
    const float* a_ds = (const float*)d_in[5];
    const float* a_c1 = (const float*)d_in[6];
    const float* a_c2 = (const float*)d_in[7];
    const float* a_c3 = (const float*)d_in[8];
    const float* pegw = (const float*)d_in[9];
    const float* g1   = (const float*)d_in[10];
    const float* b1   = (const float*)d_in[11];
    const float* g2   = (const float*)d_in[12];
    const float* b2   = (const float*)d_in[13];
    const float* g3   = (const float*)d_in[14];
    const float* b3   = (const float*)d_in[15];
    const float* gds  = (const float*)d_in[16];
    const float* bds  = (const float*)d_in[17];
    const float* lds  = (const float*)d_in[18];
    const float* lc1  = (const float*)d_in[19];
    const float* lc2  = (const float*)d_in[20];
    const float* lc3  = (const float*)d_in[21];
    float* out = (float*)d_out;

    Scratch* s = nullptr;
    cudaGetSymbolAddress((void**)&s, g_s);

    // 1) zero accumulators + per-tensor weight min/max
    prep_kernel<<<4, 1024>>>(w_ds, w_c1, w_c2, w_c3);

    // 2) bin-reconstruct all weights + KL partial sums
    recon_kernel<<<92, 256>>>(w_ds, w_c1, w_c2, w_c3,
                              a_ds, a_c1, a_c2, a_c3,
                              lds, lc1, lc2, lc3);

    // 3) fused ds (y<8, +bnds stats) and c1 (y=8..9) over x  [R5 geometry]
    adder1x1_kernel<128, true, false, false><<<dim3(13, 10, 4), 256>>>(
        x, nullptr, nullptr, 0,
        nullptr, nullptr, nullptr, nullptr, nullptr, nullptr);

    // 4) PEG depthwise (wide, 256 blocks) + bn1 stats
    peg_kernel<<<256, 256>>>(s->buf_c1, pegw, s->buf_peg,
                             s->accd + 1152, s->accd + 1216);

    // 5) conv2 3x3 with inline bn1+relu on input (+ bn2 stats) [R5 geometry]
    adder3x3_kernel<<<dim3(13, 4, 4), 256>>>(
        s->buf_peg, s->f_c2, s->buf_c2,
        s->accd + 1152, s->accd + 1216, g1, b1,
        s->accd + 512, s->accd + 576);

    // 6) conv3 1x1 with inline bn2+relu on input (+ bn3 stats) [R5 geometry]
    adder1x1_kernel<64, false, true, true><<<dim3(13, 8, 4), 256>>>(
        s->buf_c2, s->f_c3, s->buf_c3, 256,
        s->accd + 512, s->accd + 576, g2, b2, s->accd + 640, s->accd + 896);

    // 7) fused epilogue: bn3 + relu(bnds) residual + relu, and KL scalar
    final_kernel<<<784, 256>>>(g3, b3, gds, bds, out, out_size);
}